// round 2
// baseline (speedup 1.0000x reference)
#include <cuda_runtime.h>
#include <math.h>
#include <stdint.h>

#define B_  32
#define T_  127
#define S_  256
#define H_  512
#define V_  8000
#define NH_ 8
#define HD_ 64
#define G_  2048          // 4*H
#define M_BT (B_*T_)      // 4064
#define M_BS (B_*S_)      // 8192
#define SG_K 512

// ---------------- scratch (static device globals; no allocation) -------------
__device__ float g_emb [M_BT * H_];
__device__ float g_xg  [M_BT * G_];
__device__ float g_xgT [(size_t)T_ * G_ * B_];   // [t][gate_row][b]
__device__ float g_lstm[M_BT * H_];
__device__ float g_q   [M_BT * H_];
__device__ float g_k   [M_BS * H_];
__device__ float g_v   [M_BS * H_];
__device__ float g_ctx [M_BT * H_];
__device__ float g_comb[M_BT * H_];
__device__ float g_hbuf[3][B_ * H_];             // triple-buffered h state
__device__ unsigned int g_bar[128];              // per-block monotone barrier flags

// ---------------- 1) embedding gather ---------------------------------------
__global__ void k_gather(const int* __restrict__ targets,
                         const float* __restrict__ emb)
{
    int m = blockIdx.x;            // m = b*T + t
    int b = m / T_, t = m % T_;
    int tok = targets[b * 128 + t];
    const float4* src = (const float4*)(emb + (size_t)tok * H_);
    float4*       dst = (float4*)(g_emb + (size_t)m * H_);
    for (int i = threadIdx.x; i < H_ / 4; i += blockDim.x) dst[i] = src[i];
}

// ---------------- 2) generic SGEMM: C[M,N] = A[M,K] * W[N,K]^T (+biases/add) -
__global__ __launch_bounds__(256) void k_sgemm(
    const float* __restrict__ A, const float* __restrict__ W,
    const float* __restrict__ bias1, const float* __restrict__ bias2,
    const float* __restrict__ addsrc, float* __restrict__ C,
    int M, int N)
{
    __shared__ float As[16][132];
    __shared__ float Ws[16][132];
    int tid = threadIdx.x;
    int m0 = blockIdx.y * 128;
    int n0 = blockIdx.x * 128;
    int tx = tid & 15, ty = tid >> 4;
    int lrow = tid >> 1;           // 0..127
    int lk   = (tid & 1) * 8;      // 0 or 8

    float acc[8][8];
#pragma unroll
    for (int i = 0; i < 8; i++)
#pragma unroll
        for (int j = 0; j < 8; j++) acc[i][j] = 0.f;

    for (int k0 = 0; k0 < SG_K; k0 += 16) {
        // load A tile (transposed into As[k][m])
        {
            int gm = m0 + lrow;
            if (gm < M) {
                const float4* p = (const float4*)(A + (size_t)gm * SG_K + k0 + lk);
                float4 v0 = p[0], v1 = p[1];
                As[lk+0][lrow] = v0.x; As[lk+1][lrow] = v0.y;
                As[lk+2][lrow] = v0.z; As[lk+3][lrow] = v0.w;
                As[lk+4][lrow] = v1.x; As[lk+5][lrow] = v1.y;
                As[lk+6][lrow] = v1.z; As[lk+7][lrow] = v1.w;
            } else {
#pragma unroll
                for (int j = 0; j < 8; j++) As[lk+j][lrow] = 0.f;
            }
            int gn = n0 + lrow;
            if (gn < N) {
                const float4* p = (const float4*)(W + (size_t)gn * SG_K + k0 + lk);
                float4 v0 = p[0], v1 = p[1];
                Ws[lk+0][lrow] = v0.x; Ws[lk+1][lrow] = v0.y;
                Ws[lk+2][lrow] = v0.z; Ws[lk+3][lrow] = v0.w;
                Ws[lk+4][lrow] = v1.x; Ws[lk+5][lrow] = v1.y;
                Ws[lk+6][lrow] = v1.z; Ws[lk+7][lrow] = v1.w;
            } else {
#pragma unroll
                for (int j = 0; j < 8; j++) Ws[lk+j][lrow] = 0.f;
            }
        }
        __syncthreads();
#pragma unroll
        for (int k = 0; k < 16; k++) {
            float ra[8], rb[8];
#pragma unroll
            for (int i = 0; i < 8; i++) ra[i] = As[k][ty*8 + i];
#pragma unroll
            for (int j = 0; j < 8; j++) rb[j] = Ws[k][tx*8 + j];
#pragma unroll
            for (int i = 0; i < 8; i++)
#pragma unroll
                for (int j = 0; j < 8; j++) acc[i][j] += ra[i] * rb[j];
        }
        __syncthreads();
    }
#pragma unroll
    for (int i = 0; i < 8; i++) {
        int m = m0 + ty*8 + i;
        if (m >= M) continue;
#pragma unroll
        for (int j = 0; j < 8; j++) {
            int n = n0 + tx*8 + j;
            if (n >= N) continue;
            float v = acc[i][j];
            if (bias1)  v += bias1[n];
            if (bias2)  v += bias2[n];
            if (addsrc) v += addsrc[(size_t)m * N + n];
            C[(size_t)m * N + n] = v;
        }
    }
}

// ---------------- 3) transpose xg -> [t][gate_row][b] ------------------------
__global__ __launch_bounds__(256) void k_xgT()
{
    __shared__ float sm[32][33];
    int nc = blockIdx.x;           // 64 chunks of 32 gate-rows
    int t  = blockIdx.y;
    int lane = threadIdx.x & 31, w = threadIdx.x >> 5;
    for (int bb = w; bb < 32; bb += 8)
        sm[lane][bb] = g_xg[(size_t)(bb * T_ + t) * G_ + nc * 32 + lane];
    __syncthreads();
    for (int nn = w; nn < 32; nn += 8)
        g_xgT[((size_t)t * G_ + nc * 32 + nn) * 32 + lane] = sm[nn][lane];
}

// ---------------- 4) persistent LSTM ----------------------------------------
// 128 blocks x 256 threads. Block bid owns hidden units [bid*4, bid*4+4),
// i.e. 16 gate rows (local r: gate = r>>2, u = r&3, grow = gate*512 + bid*4+u).
// w_hh slice lives in SMEM for the whole kernel; h staged to SMEM each step.
#define LNB 128
#define LTH 256
#define WSM_LD 520
#define HSM_LD 516
#define LSTM_SMEM ((16*WSM_LD + 32*HSM_LD + 16*32) * 4)

__global__ __launch_bounds__(LTH) void k_lstm(const float* __restrict__ whh)
{
    extern __shared__ float sm[];
    float* w_sm = sm;                       // [16][520]
    float* h_sm = sm + 16 * WSM_LD;         // [32][516]
    float* g_sm = h_sm + 32 * HSM_LD;       // [16][32]
    int tid = threadIdx.x, bid = blockIdx.x;
    int lane = tid & 31, w = tid >> 5;

    // one-time load of this block's w_hh slice
    for (int idx = tid; idx < 16 * H_; idx += LTH) {
        int r = idx >> 9, k = idx & 511;
        int gate = r >> 2, u = r & 3;
        w_sm[r * WSM_LD + k] = whh[(size_t)(gate * H_ + bid * 4 + u) * H_ + k];
    }
    unsigned base = *((volatile unsigned*)&g_bar[bid]); // only this block writes this slot
    float c_reg = 0.f;
    int uu = tid >> 5;            // update threads tid<128: u=tid>>5, b=tid&31
    __syncthreads();

    for (int t = 0; t < T_; t++) {
        float acc0 = 0.f, acc1 = 0.f;
        if (t > 0) {
            // grid barrier: wait until all blocks posted value base + t
            unsigned target = base + (unsigned)t;
            for (;;) {
                int ok = 1;
                if (tid < LNB) {
                    unsigned v = *((volatile unsigned*)&g_bar[tid]);
                    ok = (v >= target) ? 1 : 0;
                }
                if (__syncthreads_and(ok)) break;
            }
            __threadfence();
            // stage h_{t-1} (bypass L1: not coherent across blocks)
            const float4* hb = (const float4*)g_hbuf[(t - 1) % 3];
            for (int i = tid; i < B_ * H_ / 4; i += LTH) {
                float4 v4 = __ldcg(hb + i);
                int b = i >> 7, k4 = i & 127;
                *((float4*)&h_sm[b * HSM_LD + k4 * 4]) = v4;
            }
            __syncthreads();
            // warp computes 2 gate rows x 32 batches (lane = batch)
            const float* w0 = &w_sm[(2*w    ) * WSM_LD];
            const float* w1 = &w_sm[(2*w + 1) * WSM_LD];
            const float* hr = &h_sm[lane * HSM_LD];
#pragma unroll 8
            for (int k4 = 0; k4 < 128; k4++) {
                float4 h4 = *((const float4*)&hr[k4 * 4]);
                float4 a4 = *((const float4*)&w0[k4 * 4]);
                float4 b4 = *((const float4*)&w1[k4 * 4]);
                acc0 += h4.x*a4.x + h4.y*a4.y + h4.z*a4.z + h4.w*a4.w;
                acc1 += h4.x*b4.x + h4.y*b4.y + h4.z*b4.z + h4.w*b4.w;
            }
        }
        g_sm[(2*w    ) * 32 + lane] = acc0;
        g_sm[(2*w + 1) * 32 + lane] = acc1;
        __syncthreads();
        if (tid < 128) {
            int b = lane;
            int j = bid * 4 + uu;
            const float* xt = g_xgT + (size_t)t * G_ * B_;
            float gi = g_sm[(0*4+uu)*32 + b] + xt[((size_t)(0*H_ + j)) * B_ + b];
            float gf = g_sm[(1*4+uu)*32 + b] + xt[((size_t)(1*H_ + j)) * B_ + b];
            float gg = g_sm[(2*4+uu)*32 + b] + xt[((size_t)(2*H_ + j)) * B_ + b];
            float go = g_sm[(3*4+uu)*32 + b] + xt[((size_t)(3*H_ + j)) * B_ + b];
            float i_ = 1.f / (1.f + __expf(-gi));
            float f_ = 1.f / (1.f + __expf(-gf));
            float gv = tanhf(gg);
            float o_ = 1.f / (1.f + __expf(-go));
            c_reg = f_ * c_reg + i_ * gv;
            float h = o_ * tanhf(c_reg);
            g_hbuf[t % 3][b * H_ + j] = h;
            g_lstm[(size_t)(b * T_ + t) * H_ + j] = h;
            __threadfence();
        }
        __syncthreads();
        if (tid == 0)
            *((volatile unsigned*)&g_bar[bid]) = base + (unsigned)(t + 1);
    }
}

// ---------------- 5) attention (one block per (head, batch)) ----------------
__global__ __launch_bounds__(256) void k_attn()
{
    __shared__ float q_s[64];
    __shared__ float attn_s[256];
    __shared__ float red[8];
    __shared__ float ctxp[4][64];
    int tid = threadIdx.x;
    int nh = blockIdx.x, b = blockIdx.y;
    int lane = tid & 31, w = tid >> 5;
    const float* kb = g_k + (size_t)b * S_ * H_ + nh * HD_;
    const float* vb = g_v + (size_t)b * S_ * H_ + nh * HD_;

    for (int t = 0; t < T_; t++) {
        if (tid < 64)
            q_s[tid] = g_q[(size_t)(b * T_ + t) * H_ + nh * HD_ + tid];
        __syncthreads();
        // scores: thread = key position s
        const float* kr = kb + (size_t)tid * H_;
        float sc = 0.f;
#pragma unroll
        for (int d = 0; d < 64; d += 4) {
            float4 kk = *(const float4*)(kr + d);
            sc += q_s[d]*kk.x + q_s[d+1]*kk.y + q_s[d+2]*kk.z + q_s[d+3]*kk.w;
        }
        sc *= 0.125f;
        // max
        float mx = sc;
#pragma unroll
        for (int o = 16; o; o >>= 1) mx = fmaxf(mx, __shfl_xor_sync(0xffffffffu, mx, o));
        if (lane == 0) red[w] = mx;
        __syncthreads();
        mx = red[0];
#pragma unroll
        for (int i = 1; i < 8; i++) mx = fmaxf(mx, red[i]);
        float e = __expf(sc - mx);
        float sum = e;
#pragma unroll
        for (int o = 16; o; o >>= 1) sum += __shfl_xor_sync(0xffffffffu, sum, o);
        __syncthreads();
        if (lane == 0) red[w] = sum;
        __syncthreads();
        sum = red[0] + red[1] + red[2] + red[3] + red[4] + red[5] + red[6] + red[7];
        attn_s[tid] = e * (1.f / sum);
        __syncthreads();
        // ctx: 4 s-chunks x 64 dims
        int d = tid & 63, scn = tid >> 6;
        const float* vr = vb + (size_t)(scn * 64) * H_ + d;
        float a = 0.f;
#pragma unroll 8
        for (int s = 0; s < 64; s++) a += attn_s[scn * 64 + s] * vr[(size_t)s * H_];
        ctxp[scn][d] = a;
        __syncthreads();
        if (tid < 64)
            g_ctx[(size_t)(b * T_ + t) * H_ + nh * HD_ + tid] =
                ctxp[0][tid] + ctxp[1][tid] + ctxp[2][tid] + ctxp[3][tid];
        __syncthreads();
    }
}

// ---------------- launcher ---------------------------------------------------
extern "C" void kernel_launch(void* const* d_in, const int* in_sizes, int n_in,
                              void* d_out, int out_size)
{
    const int*   targets    = (const int*)  d_in[0];
    const float* enc        = (const float*)d_in[1];
    const float* embedding  = (const float*)d_in[2];
    const float* w_ih       = (const float*)d_in[3];
    const float* w_hh       = (const float*)d_in[4];
    const float* b_ih       = (const float*)d_in[5];
    const float* b_hh       = (const float*)d_in[6];
    const float* in_proj_w  = (const float*)d_in[7];
    const float* in_proj_b  = (const float*)d_in[8];
    const float* out_proj_w = (const float*)d_in[9];
    const float* out_proj_b = (const float*)d_in[10];
    const float* fc_w       = (const float*)d_in[11];
    const float* fc_b       = (const float*)d_in[12];
    float* out = (float*)d_out;

    float *p_emb, *p_xg, *p_lstm, *p_q, *p_k, *p_v, *p_ctx, *p_comb;
    cudaGetSymbolAddress((void**)&p_emb,  g_emb);
    cudaGetSymbolAddress((void**)&p_xg,   g_xg);
    cudaGetSymbolAddress((void**)&p_lstm, g_lstm);
    cudaGetSymbolAddress((void**)&p_q,    g_q);
    cudaGetSymbolAddress((void**)&p_k,    g_k);
    cudaGetSymbolAddress((void**)&p_v,    g_v);
    cudaGetSymbolAddress((void**)&p_ctx,  g_ctx);
    cudaGetSymbolAddress((void**)&p_comb, g_comb);

    cudaFuncSetAttribute(k_lstm, cudaFuncAttributeMaxDynamicSharedMemorySize,
                         LSTM_SMEM);

    // 1) embedding gather
    k_gather<<<M_BT, 128>>>(targets, embedding);
    // 2) xg = emb @ w_ih^T + b_ih + b_hh
    k_sgemm<<<dim3(G_/128, (M_BT+127)/128), 256>>>(p_emb, w_ih, b_ih, b_hh,
                                                   nullptr, p_xg, M_BT, G_);
    // 3) transpose xg to [t][gate_row][b]
    k_xgT<<<dim3(64, T_), 256>>>();
    // 4) persistent LSTM over 127 steps
    k_lstm<<<LNB, LTH, LSTM_SMEM>>>(w_hh);
    // 5) q/k/v projections
    k_sgemm<<<dim3(4, (M_BT+127)/128), 256>>>(p_lstm, in_proj_w, in_proj_b,
                                              nullptr, nullptr, p_q, M_BT, H_);
    k_sgemm<<<dim3(4, M_BS/128), 256>>>(enc, in_proj_w + (size_t)H_*H_,
                                        in_proj_b + H_, nullptr, nullptr,
                                        p_k, M_BS, H_);
    k_sgemm<<<dim3(4, M_BS/128), 256>>>(enc, in_proj_w + (size_t)2*H_*H_,
                                        in_proj_b + 2*H_, nullptr, nullptr,
                                        p_v, M_BS, H_);
    // 6) attention
    k_attn<<<dim3(NH_, B_), 256>>>();
    // 7) combined = ctx @ out_proj^T + b + lstm_out  (fused residual add)
    k_sgemm<<<dim3(4, (M_BT+127)/128), 256>>>(p_ctx, out_proj_w, out_proj_b,
                                              nullptr, p_lstm, p_comb, M_BT, H_);
    // 8) logits = combined @ fc_w^T + fc_b
    k_sgemm<<<dim3((V_+127)/128, (M_BT+127)/128), 256>>>(p_comb, fc_w, fc_b,
                                                         nullptr, nullptr, out,
                                                         M_BT, V_);
}

// round 3
// speedup vs baseline: 1.0845x; 1.0845x over previous
#include <cuda_runtime.h>
#include <math.h>
#include <stdint.h>

#define B_  32
#define T_  127
#define S_  256
#define H_  512
#define V_  8000
#define NH_ 8
#define HD_ 64
#define G_  2048          // 4*H
#define M_BT (B_*T_)      // 4064
#define M_BS (B_*S_)      // 8192
#define SG_K 512

// ---------------- scratch (static device globals; no allocation) -------------
__device__ float g_emb [M_BT * H_];
__device__ float g_xg  [M_BT * G_];
__device__ float g_xgT [(size_t)T_ * G_ * B_];   // [t][gate_row][b]
__device__ float g_lstm[M_BT * H_];
__device__ float g_q   [M_BT * H_];
__device__ float g_k   [M_BS * H_];
__device__ float g_v   [M_BS * H_];
__device__ float g_ctx [M_BT * H_];
__device__ float g_comb[M_BT * H_];
__device__ float g_hbufT[3][H_ * B_];            // h state, [j][b] layout, triple buffered
__device__ unsigned int g_bar[128];              // per-block monotone barrier flags

// ---------------- 1) embedding gather ---------------------------------------
__global__ void k_gather(const int* __restrict__ targets,
                         const float* __restrict__ emb)
{
    int m = blockIdx.x;            // m = b*T + t
    int b = m / T_, t = m % T_;
    int tok = targets[b * 128 + t];
    const float4* src = (const float4*)(emb + (size_t)tok * H_);
    float4*       dst = (float4*)(g_emb + (size_t)m * H_);
    for (int i = threadIdx.x; i < H_ / 4; i += blockDim.x) dst[i] = src[i];
}

// ---------------- 2) FFMA SGEMM (kept for xg only; error isolation) ----------
__global__ __launch_bounds__(256) void k_sgemm(
    const float* __restrict__ A, const float* __restrict__ W,
    const float* __restrict__ bias1, const float* __restrict__ bias2,
    float* __restrict__ C, int M, int N)
{
    __shared__ float As[16][132];
    __shared__ float Ws[16][132];
    int tid = threadIdx.x;
    int m0 = blockIdx.y * 128;
    int n0 = blockIdx.x * 128;
    int tx = tid & 15, ty = tid >> 4;
    int lrow = tid >> 1;           // 0..127
    int lk   = (tid & 1) * 8;      // 0 or 8

    float acc[8][8];
#pragma unroll
    for (int i = 0; i < 8; i++)
#pragma unroll
        for (int j = 0; j < 8; j++) acc[i][j] = 0.f;

    for (int k0 = 0; k0 < SG_K; k0 += 16) {
        {
            int gm = m0 + lrow; if (gm > M - 1) gm = M - 1;
            const float4* p = (const float4*)(A + (size_t)gm * SG_K + k0 + lk);
            float4 v0 = p[0], v1 = p[1];
            As[lk+0][lrow] = v0.x; As[lk+1][lrow] = v0.y;
            As[lk+2][lrow] = v0.z; As[lk+3][lrow] = v0.w;
            As[lk+4][lrow] = v1.x; As[lk+5][lrow] = v1.y;
            As[lk+6][lrow] = v1.z; As[lk+7][lrow] = v1.w;
            int gn = n0 + lrow; if (gn > N - 1) gn = N - 1;
            const float4* q = (const float4*)(W + (size_t)gn * SG_K + k0 + lk);
            float4 w0 = q[0], w1 = q[1];
            Ws[lk+0][lrow] = w0.x; Ws[lk+1][lrow] = w0.y;
            Ws[lk+2][lrow] = w0.z; Ws[lk+3][lrow] = w0.w;
            Ws[lk+4][lrow] = w1.x; Ws[lk+5][lrow] = w1.y;
            Ws[lk+6][lrow] = w1.z; Ws[lk+7][lrow] = w1.w;
        }
        __syncthreads();
#pragma unroll
        for (int k = 0; k < 16; k++) {
            float ra[8], rb[8];
#pragma unroll
            for (int i = 0; i < 8; i++) ra[i] = As[k][ty*8 + i];
#pragma unroll
            for (int j = 0; j < 8; j++) rb[j] = Ws[k][tx*8 + j];
#pragma unroll
            for (int i = 0; i < 8; i++)
#pragma unroll
                for (int j = 0; j < 8; j++) acc[i][j] += ra[i] * rb[j];
        }
        __syncthreads();
    }
#pragma unroll
    for (int i = 0; i < 8; i++) {
        int m = m0 + ty*8 + i;
        if (m >= M) continue;
#pragma unroll
        for (int j = 0; j < 8; j++) {
            int n = n0 + tx*8 + j;
            if (n >= N) continue;
            float v = acc[i][j];
            if (bias1)  v += bias1[n];
            if (bias2)  v += bias2[n];
            C[(size_t)m * N + n] = v;
        }
    }
}

// ---------------- 2b) tf32 tensor-core GEMM ----------------------------------
// C[M,N] = A[M,512] @ W[N,512]^T (+bias)(+addsrc). 128x128 tile, BK=16,
// 8 warps (4x2), warp tile 32x64, mma.m16n8k8 tf32.
__device__ __forceinline__ unsigned f2tf(float x) {
    unsigned u;
    asm("cvt.rna.tf32.f32 %0, %1;" : "=r"(u) : "f"(x));
    return u;
}

#define TLD 136   // padded leading dim: conflict-free fragment loads

#define MMA_TF32(d0,d1,d2,d3,a0,a1,a2,a3,b0,b1)                             \
    asm volatile("mma.sync.aligned.m16n8k8.row.col.f32.tf32.tf32.f32 "      \
                 "{%0,%1,%2,%3},{%4,%5,%6,%7},{%8,%9},{%0,%1,%2,%3};"       \
                 : "+f"(d0), "+f"(d1), "+f"(d2), "+f"(d3)                   \
                 : "r"(a0), "r"(a1), "r"(a2), "r"(a3), "r"(b0), "r"(b1))

__global__ __launch_bounds__(256) void k_tf32(
    const float* __restrict__ A, const float* __restrict__ W,
    const float* __restrict__ bias, const float* __restrict__ addsrc,
    float* __restrict__ C, int M, int N)
{
    __shared__ unsigned As[16 * TLD];
    __shared__ unsigned Ws[16 * TLD];
    int tid  = threadIdx.x;
    int lane = tid & 31, warp = tid >> 5;
    int warpM = warp & 3, warpN = warp >> 2;   // warp tile origin (32m, 64n)
    int m0 = blockIdx.y * 128;
    int n0 = blockIdx.x * 128;
    int lrow = tid >> 1;           // 0..127
    int lk   = (tid & 1) * 8;      // 0 or 8

    float acc[2][8][4];
#pragma unroll
    for (int i = 0; i < 2; i++)
#pragma unroll
        for (int j = 0; j < 8; j++)
#pragma unroll
            for (int r = 0; r < 4; r++) acc[i][j][r] = 0.f;

    int gm = m0 + lrow; if (gm > M - 1) gm = M - 1;
    int gn = n0 + lrow; if (gn > N - 1) gn = N - 1;
    const float4* Arow = (const float4*)(A + (size_t)gm * SG_K);
    const float4* Wrow = (const float4*)(W + (size_t)gn * SG_K);

    int c = lane & 3, g = lane >> 2;

    for (int k0 = 0; k0 < SG_K; k0 += 16) {
        float4 av0 = Arow[(k0 + lk) >> 2], av1 = Arow[((k0 + lk) >> 2) + 1];
        float4 wv0 = Wrow[(k0 + lk) >> 2], wv1 = Wrow[((k0 + lk) >> 2) + 1];
        As[(lk+0)*TLD + lrow] = f2tf(av0.x); As[(lk+1)*TLD + lrow] = f2tf(av0.y);
        As[(lk+2)*TLD + lrow] = f2tf(av0.z); As[(lk+3)*TLD + lrow] = f2tf(av0.w);
        As[(lk+4)*TLD + lrow] = f2tf(av1.x); As[(lk+5)*TLD + lrow] = f2tf(av1.y);
        As[(lk+6)*TLD + lrow] = f2tf(av1.z); As[(lk+7)*TLD + lrow] = f2tf(av1.w);
        Ws[(lk+0)*TLD + lrow] = f2tf(wv0.x); Ws[(lk+1)*TLD + lrow] = f2tf(wv0.y);
        Ws[(lk+2)*TLD + lrow] = f2tf(wv0.z); Ws[(lk+3)*TLD + lrow] = f2tf(wv0.w);
        Ws[(lk+4)*TLD + lrow] = f2tf(wv1.x); Ws[(lk+5)*TLD + lrow] = f2tf(wv1.y);
        Ws[(lk+6)*TLD + lrow] = f2tf(wv1.z); Ws[(lk+7)*TLD + lrow] = f2tf(wv1.w);
        __syncthreads();
#pragma unroll
        for (int kk = 0; kk < 16; kk += 8) {
            unsigned af[2][4];
#pragma unroll
            for (int mi = 0; mi < 2; mi++) {
                int mb = warpM*32 + mi*16 + g;
                af[mi][0] = As[(kk + c    )*TLD + mb    ];
                af[mi][1] = As[(kk + c    )*TLD + mb + 8];
                af[mi][2] = As[(kk + c + 4)*TLD + mb    ];
                af[mi][3] = As[(kk + c + 4)*TLD + mb + 8];
            }
            unsigned bf[8][2];
#pragma unroll
            for (int ni = 0; ni < 8; ni++) {
                int nb = warpN*64 + ni*8 + g;
                bf[ni][0] = Ws[(kk + c    )*TLD + nb];
                bf[ni][1] = Ws[(kk + c + 4)*TLD + nb];
            }
#pragma unroll
            for (int mi = 0; mi < 2; mi++)
#pragma unroll
                for (int ni = 0; ni < 8; ni++)
                    MMA_TF32(acc[mi][ni][0], acc[mi][ni][1],
                             acc[mi][ni][2], acc[mi][ni][3],
                             af[mi][0], af[mi][1], af[mi][2], af[mi][3],
                             bf[ni][0], bf[ni][1]);
        }
        __syncthreads();
    }
    // epilogue: c0:(g, 2q) c1:(g, 2q+1) c2:(g+8, 2q) c3:(g+8, 2q+1)
    int q = lane & 3;
#pragma unroll
    for (int mi = 0; mi < 2; mi++) {
        int m_lo = m0 + warpM*32 + mi*16 + g;
        int m_hi = m_lo + 8;
#pragma unroll
        for (int ni = 0; ni < 8; ni++) {
            int n = n0 + warpN*64 + ni*8 + 2*q;
            if (n >= N) continue;     // N even, n even -> n+1 < N too
            float b0v = 0.f, b1v = 0.f;
            if (bias) { b0v = bias[n]; b1v = bias[n+1]; }
            if (m_lo < M) {
                float v0 = acc[mi][ni][0] + b0v;
                float v1 = acc[mi][ni][1] + b1v;
                if (addsrc) {
                    v0 += addsrc[(size_t)m_lo * N + n];
                    v1 += addsrc[(size_t)m_lo * N + n + 1];
                }
                *(float2*)(C + (size_t)m_lo * N + n) = make_float2(v0, v1);
            }
            if (m_hi < M) {
                float v2 = acc[mi][ni][2] + b0v;
                float v3 = acc[mi][ni][3] + b1v;
                if (addsrc) {
                    v2 += addsrc[(size_t)m_hi * N + n];
                    v3 += addsrc[(size_t)m_hi * N + n + 1];
                }
                *(float2*)(C + (size_t)m_hi * N + n) = make_float2(v2, v3);
            }
        }
    }
}

// ---------------- 3) transpose xg -> [t][gate_row][b] ------------------------
__global__ __launch_bounds__(256) void k_xgT()
{
    __shared__ float sm[32][33];
    int nc = blockIdx.x;           // 64 chunks of 32 gate-rows
    int t  = blockIdx.y;
    int lane = threadIdx.x & 31, w = threadIdx.x >> 5;
    for (int bb = w; bb < 32; bb += 8)
        sm[lane][bb] = g_xg[(size_t)(bb * T_ + t) * G_ + nc * 32 + lane];
    __syncthreads();
    for (int nn = w; nn < 32; nn += 8)
        g_xgT[((size_t)t * G_ + nc * 32 + nn) * 32 + lane] = sm[nn][lane];
}

// ---------------- 4) persistent LSTM ----------------------------------------
// 128 blocks x 256 threads. Block bid owns hidden units [bid*4, bid*4+4)
// = 16 gate rows. h kept in [k][b] layout (stride 32, conflict-free).
// 4 compute warps x 4 rows each; w read as float4 smem broadcast.
#define LNB 128
#define LTH 256
#define LSTM_SMEM ((16*512 + 512*32 + 16*32) * 4)

__global__ __launch_bounds__(LTH) void k_lstm(const float* __restrict__ whh)
{
    extern __shared__ float sm[];
    float* w_sm = sm;                 // [16][512]  row r: gate=r>>2, u=r&3
    float* h_sm = sm + 16 * 512;      // [512][32]  h[k][b]
    float* g_sm = h_sm + 512 * 32;    // [16][32]
    int tid = threadIdx.x, bid = blockIdx.x;
    int lane = tid & 31, warp = tid >> 5;

    for (int idx = tid; idx < 16 * 512; idx += LTH) {
        int r = idx >> 9, k = idx & 511;
        int gate = r >> 2, u = r & 3;
        w_sm[idx] = whh[(size_t)(gate * H_ + bid * 4 + u) * H_ + k];
    }
    unsigned base = *((volatile unsigned*)&g_bar[bid]);
    float c_reg = 0.f;
    int uu = tid >> 5;                // update threads tid<128: u=uu, b=lane
    __syncthreads();

    for (int t = 0; t < T_; t++) {
        if (t > 0) {
            unsigned target = base + (unsigned)t;
            for (;;) {
                int ok = 1;
                if (tid < LNB) {
                    unsigned v = *((volatile unsigned*)&g_bar[tid]);
                    ok = (v >= target) ? 1 : 0;
                }
                if (__syncthreads_and(ok)) break;
            }
            __threadfence();
            const float4* hb = (const float4*)g_hbufT[(t - 1) % 3];
            float4* hd = (float4*)h_sm;
            for (int i = tid; i < H_ * B_ / 4; i += LTH)
                hd[i] = __ldcg(hb + i);
            __syncthreads();
        }
        float a0 = 0.f, a1 = 0.f, a2 = 0.f, a3 = 0.f;
        if (t > 0 && warp < 4) {
            const float* w0 = &w_sm[(warp*4 + 0) * 512];
            const float* w1 = &w_sm[(warp*4 + 1) * 512];
            const float* w2 = &w_sm[(warp*4 + 2) * 512];
            const float* w3 = &w_sm[(warp*4 + 3) * 512];
#pragma unroll 4
            for (int k = 0; k < 512; k += 4) {
                float h0 = h_sm[(k+0)*32 + lane];
                float h1 = h_sm[(k+1)*32 + lane];
                float h2 = h_sm[(k+2)*32 + lane];
                float h3 = h_sm[(k+3)*32 + lane];
                float4 wa = *(const float4*)&w0[k];
                float4 wb = *(const float4*)&w1[k];
                float4 wc = *(const float4*)&w2[k];
                float4 wd = *(const float4*)&w3[k];
                a0 += h0*wa.x + h1*wa.y + h2*wa.z + h3*wa.w;
                a1 += h0*wb.x + h1*wb.y + h2*wb.z + h3*wb.w;
                a2 += h0*wc.x + h1*wc.y + h2*wc.z + h3*wc.w;
                a3 += h0*wd.x + h1*wd.y + h2*wd.z + h3*wd.w;
            }
        }
        if (warp < 4) {
            g_sm[(warp*4 + 0)*32 + lane] = a0;
            g_sm[(warp*4 + 1)*32 + lane] = a1;
            g_sm[(warp*4 + 2)*32 + lane] = a2;
            g_sm[(warp*4 + 3)*32 + lane] = a3;
        }
        __syncthreads();
        if (tid < 128) {
            int b = lane;
            int j = bid * 4 + uu;
            const float* xt = g_xgT + (size_t)t * G_ * B_;
            float gi = g_sm[(0*4+uu)*32 + b] + xt[((size_t)(0*H_ + j)) * B_ + b];
            float gf = g_sm[(1*4+uu)*32 + b] + xt[((size_t)(1*H_ + j)) * B_ + b];
            float gg = g_sm[(2*4+uu)*32 + b] + xt[((size_t)(2*H_ + j)) * B_ + b];
            float go = g_sm[(3*4+uu)*32 + b] + xt[((size_t)(3*H_ + j)) * B_ + b];
            float i_ = 1.f / (1.f + __expf(-gi));
            float f_ = 1.f / (1.f + __expf(-gf));
            float gv = tanhf(gg);
            float o_ = 1.f / (1.f + __expf(-go));
            c_reg = f_ * c_reg + i_ * gv;
            float h = o_ * tanhf(c_reg);
            g_hbufT[t % 3][j * B_ + b] = h;                 // [j][b], coalesced
            g_lstm[(size_t)(b * T_ + t) * H_ + j] = h;
            __threadfence();
        }
        __syncthreads();
        if (tid == 0)
            *((volatile unsigned*)&g_bar[bid]) = base + (unsigned)(t + 1);
    }
}

// ---------------- 5) attention (one block per (head, batch)) ----------------
__global__ __launch_bounds__(256) void k_attn()
{
    __shared__ float q_s[64];
    __shared__ float attn_s[256];
    __shared__ float red[8];
    __shared__ float ctxp[4][64];
    int tid = threadIdx.x;
    int nh = blockIdx.x, b = blockIdx.y;
    int lane = tid & 31, w = tid >> 5;
    const float* kb = g_k + (size_t)b * S_ * H_ + nh * HD_;
    const float* vb = g_v + (size_t)b * S_ * H_ + nh * HD_;

    for (int t = 0; t < T_; t++) {
        if (tid < 64)
            q_s[tid] = g_q[(size_t)(b * T_ + t) * H_ + nh * HD_ + tid];
        __syncthreads();
        const float* kr = kb + (size_t)tid * H_;
        float sc = 0.f;
#pragma unroll
        for (int d = 0; d < 64; d += 4) {
            float4 kk = *(const float4*)(kr + d);
            sc += q_s[d]*kk.x + q_s[d+1]*kk.y + q_s[d+2]*kk.z + q_s[d+3]*kk.w;
        }
        sc *= 0.125f;
        float mx = sc;
#pragma unroll
        for (int o = 16; o; o >>= 1) mx = fmaxf(mx, __shfl_xor_sync(0xffffffffu, mx, o));
        if (lane == 0) red[w] = mx;
        __syncthreads();
        mx = red[0];
#pragma unroll
        for (int i = 1; i < 8; i++) mx = fmaxf(mx, red[i]);
        float e = __expf(sc - mx);
        float sum = e;
#pragma unroll
        for (int o = 16; o; o >>= 1) sum += __shfl_xor_sync(0xffffffffu, sum, o);
        __syncthreads();
        if (lane == 0) red[w] = sum;
        __syncthreads();
        sum = red[0] + red[1] + red[2] + red[3] + red[4] + red[5] + red[6] + red[7];
        attn_s[tid] = e * (1.f / sum);
        __syncthreads();
        int d = tid & 63, scn = tid >> 6;
        const float* vr = vb + (size_t)(scn * 64) * H_ + d;
        float a = 0.f;
#pragma unroll 8
        for (int s = 0; s < 64; s++) a += attn_s[scn * 64 + s] * vr[(size_t)s * H_];
        ctxp[scn][d] = a;
        __syncthreads();
        if (tid < 64)
            g_ctx[(size_t)(b * T_ + t) * H_ + nh * HD_ + tid] =
                ctxp[0][tid] + ctxp[1][tid] + ctxp[2][tid] + ctxp[3][tid];
        __syncthreads();
    }
}

// ---------------- launcher ---------------------------------------------------
extern "C" void kernel_launch(void* const* d_in, const int* in_sizes, int n_in,
                              void* d_out, int out_size)
{
    const int*   targets    = (const int*)  d_in[0];
    const float* enc        = (const float*)d_in[1];
    const float* embedding  = (const float*)d_in[2];
    const float* w_ih       = (const float*)d_in[3];
    const float* w_hh       = (const float*)d_in[4];
    const float* b_ih       = (const float*)d_in[5];
    const float* b_hh       = (const float*)d_in[6];
    const float* in_proj_w  = (const float*)d_in[7];
    const float* in_proj_b  = (const float*)d_in[8];
    const float* out_proj_w = (const float*)d_in[9];
    const float* out_proj_b = (const float*)d_in[10];
    const float* fc_w       = (const float*)d_in[11];
    const float* fc_b       = (const float*)d_in[12];
    float* out = (float*)d_out;

    float *p_emb, *p_xg, *p_lstm, *p_q, *p_k, *p_v, *p_ctx, *p_comb;
    cudaGetSymbolAddress((void**)&p_emb,  g_emb);
    cudaGetSymbolAddress((void**)&p_xg,   g_xg);
    cudaGetSymbolAddress((void**)&p_lstm, g_lstm);
    cudaGetSymbolAddress((void**)&p_q,    g_q);
    cudaGetSymbolAddress((void**)&p_k,    g_k);
    cudaGetSymbolAddress((void**)&p_v,    g_v);
    cudaGetSymbolAddress((void**)&p_ctx,  g_ctx);
    cudaGetSymbolAddress((void**)&p_comb, g_comb);

    cudaFuncSetAttribute(k_lstm, cudaFuncAttributeMaxDynamicSharedMemorySize,
                         LSTM_SMEM);

    // 1) embedding gather
    k_gather<<<M_BT, 128>>>(targets, embedding);
    // 2) xg = emb @ w_ih^T + b_ih + b_hh   (fp32 FFMA: keeps recurrence exact)
    k_sgemm<<<dim3(G_/128, (M_BT+127)/128), 256>>>(p_emb, w_ih, b_ih, b_hh,
                                                   p_xg, M_BT, G_);
    // 3) transpose xg to [t][gate_row][b]
    k_xgT<<<dim3(64, T_), 256>>>();
    // 4) persistent LSTM over 127 steps
    k_lstm<<<LNB, LTH, LSTM_SMEM>>>(w_hh);
    // 5) q/k/v projections (tf32 tensor cores)
    k_tf32<<<dim3(4, (M_BT+127)/128), 256>>>(p_lstm, in_proj_w, in_proj_b,
                                             nullptr, p_q, M_BT, H_);
    k_tf32<<<dim3(4, M_BS/128), 256>>>(enc, in_proj_w + (size_t)H_*H_,
                                       in_proj_b + H_, nullptr, p_k, M_BS, H_);
    k_tf32<<<dim3(4, M_BS/128), 256>>>(enc, in_proj_w + (size_t)2*H_*H_,
                                       in_proj_b + 2*H_, nullptr, p_v, M_BS, H_);
    // 6) attention
    k_attn<<<dim3(NH_, B_), 256>>>();
    // 7) combined = ctx @ out_proj^T + b + lstm_out (tf32, fused residual)
    k_tf32<<<dim3(4, (M_BT+127)/128), 256>>>(p_ctx, out_proj_w, out_proj_b,
                                             p_lstm, p_comb, M_BT, H_);
    // 8) logits = combined @ fc_w^T + fc_b (tf32)
    k_tf32<<<dim3((V_+127)/128, (M_BT+127)/128), 256>>>(p_comb, fc_w, fc_b,
                                                        nullptr, out, M_BT, V_);
}